// round 10
// baseline (speedup 1.0000x reference)
#include <cuda_runtime.h>
#include <cstdint>

// ---------------- problem constants ----------------
#define B_   1024
#define S_   200
#define D_   64
#define NI_  4
#define E_   256            // NI * D
#define INTEREST_ELEMS (B_ * NI_ * D_)   // 262144, adj follows at this offset

// ---------------- device scratch (static; no runtime alloc) ----------------
__device__ float g_uprof[B_ * D_];                       // 256 KB
__device__ float g_item[(long long)B_ * S_ * D_];        // 52.4 MB
__device__ float g_hat [(long long)S_ * B_ * E_];        // 209.7 MB, [s][rank][e]
__device__ int   g_cnt [S_];                             // active-b count per s
__device__ int   g_blist[S_ * B_];                       // [s][rank] -> b
__device__ int   g_rank [S_ * B_];                       // [s][b] -> rank

// ---------------- cp.async helpers ----------------
#define CP_ASYNC16(dst_u32, src_ptr) \
    asm volatile("cp.async.cg.shared.global [%0], [%1], 16;" \
                 :: "r"(dst_u32), "l"(src_ptr))
#define CP_COMMIT_WAIT() \
    asm volatile("cp.async.commit_group;\ncp.async.wait_group 0;" ::: "memory")

// ---------------- tf32 mma helpers ----------------
__device__ __forceinline__ uint32_t f2tf(float x) {
    uint32_t u;
    asm("cvt.rna.tf32.f32 %0, %1;" : "=r"(u) : "f"(x));
    return u;
}

__device__ __forceinline__ void mma8(float* d, const uint32_t* a,
                                     uint32_t b0, uint32_t b1) {
    asm volatile(
        "mma.sync.aligned.m16n8k8.row.col.f32.tf32.tf32.f32 "
        "{%0,%1,%2,%3}, {%4,%5,%6,%7}, {%8,%9}, {%0,%1,%2,%3};"
        : "+f"(d[0]), "+f"(d[1]), "+f"(d[2]), "+f"(d[3])
        : "r"(a[0]), "r"(a[1]), "r"(a[2]), "r"(a[3]), "r"(b0), "r"(b1));
}

#define LDA 68     // smem row stride (uint32); conflict-free fragment LDS
#define SMEM_GEMM_BYTES (2 * 128 * LDA * 4)   // 69632

// 128x128x64 block tile, 8 warps of 32x64 each.
__device__ __forceinline__ void mma_core(const uint32_t* __restrict__ As,
                                         const uint32_t* __restrict__ Bs,
                                         int tid, float acc[2][8][4]) {
    const int lane = tid & 31, wid = tid >> 5;
    const int g = lane >> 2, t = lane & 3;
    const int m0 = (wid & 3) * 32, n0 = (wid >> 2) * 64;
    #pragma unroll
    for (int k0 = 0; k0 < 64; k0 += 8) {
        uint32_t a[2][4];
        #pragma unroll
        for (int mf = 0; mf < 2; ++mf) {
            const uint32_t* p = As + (m0 + 16 * mf + g) * LDA + k0 + t;
            a[mf][0] = p[0];
            a[mf][1] = p[8 * LDA];
            a[mf][2] = p[4];
            a[mf][3] = p[8 * LDA + 4];
        }
        #pragma unroll
        for (int nf = 0; nf < 8; ++nf) {
            const uint32_t* p = Bs + (n0 + 8 * nf + g) * LDA + k0 + t;
            uint32_t b0v = p[0], b1v = p[4];
            mma8(acc[0][nf], a[0], b0v, b1v);
            mma8(acc[1][nf], a[1], b0v, b1v);
        }
    }
}

// ====================================================================
// K1: user profile (+ zero the per-s active counters)
// ====================================================================
__global__ __launch_bounds__(256) void uprof_kernel(
    const int* __restrict__ uid, const int* __restrict__ age,
    const int* __restrict__ gender, const int* __restrict__ occup,
    const float* __restrict__ ue, const float* __restrict__ at,
    const float* __restrict__ gt, const float* __restrict__ ot)
{
    if (blockIdx.x == 0 && threadIdx.x < S_) g_cnt[threadIdx.x] = 0;
    int idx = blockIdx.x * 256 + threadIdx.x;
    int b = idx >> 6, d = idx & 63;
    float v = ue[(size_t)uid[b]    * 64 + d]
            + gt[(size_t)gender[b] * 64 + d]
            + at[(size_t)age[b]    * 64 + d]
            + ot[(size_t)occup[b]  * 64 + d];
    g_uprof[idx] = 0.25f * v;
}

// ====================================================================
// K2: item_his = mid_emb[mid_his]*mask  (+ build per-s active-b lists)
// ====================================================================
__global__ __launch_bounds__(256) void gather_kernel(
    const int* __restrict__ mid_his, const float* __restrict__ mask,
    const float* __restrict__ mid_emb)
{
    int t  = blockIdx.x * 256 + threadIdx.x;
    int bs = t >> 4, q = t & 15;
    int mi = mid_his[bs];
    float m = mask[bs];
    float4 e = ((const float4*)mid_emb)[(size_t)mi * 16 + q];
    float4 it;
    it.x = e.x * m;  it.y = e.y * m;  it.z = e.z * m;  it.w = e.w * m;
    ((float4*)g_item)[(size_t)bs * 16 + q] = it;

    if (q == 0 && m != 0.f) {
        int b = bs / S_, s = bs - b * S_;
        int r = atomicAdd(&g_cnt[s], 1);
        g_blist[s * B_ + r] = b;
        g_rank [s * B_ + b] = r;
    }
}

// ====================================================================
// K3: adj — tf32 tensor cores, tile 128x128, grid (2,2,B)
// ====================================================================
__global__ __launch_bounds__(256) void adj_kernel(
    const float* __restrict__ mask, float* __restrict__ out)
{
    extern __shared__ uint32_t sh[];
    uint32_t* As = sh;
    uint32_t* Bs = sh + 128 * LDA;
    __shared__ float msk[256];

    const int b  = blockIdx.z;
    const int i0 = blockIdx.y * 128;
    const int j0 = blockIdx.x * 128;
    const int tid = threadIdx.x;
    const float* It = g_item + (size_t)b * (S_ * D_);

    msk[tid] = (tid < S_) ? mask[b * S_ + tid] : 0.f;

    #pragma unroll
    for (int p = 0; p < 8; ++p) {
        int q = tid + p * 256;
        int r = q >> 4, c4 = q & 15;
        float4 up = ((const float4*)g_uprof)[b * 16 + c4];
        float4 av = make_float4(0.f, 0.f, 0.f, 0.f);
        float4 bv = make_float4(0.f, 0.f, 0.f, 0.f);
        if (i0 + r < S_) {
            float4 iv = *(const float4*)(It + (size_t)(i0 + r) * 64 + c4 * 4);
            av.x = iv.x * up.x; av.y = iv.y * up.y;
            av.z = iv.z * up.z; av.w = iv.w * up.w;
        }
        if (j0 + r < S_) bv = *(const float4*)(It + (size_t)(j0 + r) * 64 + c4 * 4);
        uint4 at4 = make_uint4(f2tf(av.x), f2tf(av.y), f2tf(av.z), f2tf(av.w));
        uint4 bt4 = make_uint4(f2tf(bv.x), f2tf(bv.y), f2tf(bv.z), f2tf(bv.w));
        *(uint4*)(As + r * LDA + c4 * 4) = at4;
        *(uint4*)(Bs + r * LDA + c4 * 4) = bt4;
    }
    __syncthreads();

    float acc[2][8][4] = {};
    mma_core(As, Bs, tid, acc);

    const int lane = tid & 31, wid = tid >> 5;
    const int g = lane >> 2, t = lane & 3;
    const int m0 = (wid & 3) * 32, n0 = (wid >> 2) * 64;
    float* outb = out + (size_t)b * (S_ * S_);

    #pragma unroll
    for (int mf = 0; mf < 2; ++mf) {
        #pragma unroll
        for (int nf = 0; nf < 8; ++nf) {
            int i = i0 + m0 + 16 * mf + g;
            int j = j0 + n0 + 8 * nf + 2 * t;
            if (j < S_) {
                float mj0 = msk[j], mj1 = msk[j + 1];
                if (i < S_) {
                    float mi = msk[i];
                    float s0 = 1.f / (1.f + __expf(-acc[mf][nf][0]));
                    float s1 = 1.f / (1.f + __expf(-acc[mf][nf][1]));
                    *(float2*)(outb + (size_t)i * S_ + j) =
                        make_float2(s0 * mi * mj0, s1 * mi * mj1);
                }
                if (i + 8 < S_) {
                    float mi = msk[i + 8];
                    float s2 = 1.f / (1.f + __expf(-acc[mf][nf][2]));
                    float s3 = 1.f / (1.f + __expf(-acc[mf][nf][3]));
                    *(float2*)(outb + (size_t)(i + 8) * S_ + j) =
                        make_float2(s2 * mi * mj0, s3 * mi * mj1);
                }
            }
        }
    }
}

// ====================================================================
// K4: hat — tf32 tensor cores, ACTIVE b-rows only, compacted output.
// ====================================================================
__global__ __launch_bounds__(256) void hat_kernel(const float* __restrict__ w)
{
    const int s   = blockIdx.z;
    const int cnt = g_cnt[s];
    const int b0  = blockIdx.y * 128;
    if (b0 >= cnt) return;
    const int e0  = blockIdx.x * 128;
    const int tid = threadIdx.x;

    extern __shared__ uint32_t sh[];
    uint32_t* As = sh;
    uint32_t* Bs = sh + 128 * LDA;

    #pragma unroll
    for (int p = 0; p < 8; ++p) {
        int q = tid + p * 256;
        int r = q >> 4, c4 = q & 15;
        float4 av = make_float4(0.f, 0.f, 0.f, 0.f);
        if (b0 + r < cnt) {
            int bidx = g_blist[s * B_ + b0 + r];
            av = *(const float4*)(g_item + ((size_t)bidx * S_ + s) * 64 + c4 * 4);
        }
        float4 bv = *(const float4*)(w + ((size_t)s * E_ + (e0 + r)) * 64 + c4 * 4);
        uint4 at4 = make_uint4(f2tf(av.x), f2tf(av.y), f2tf(av.z), f2tf(av.w));
        uint4 bt4 = make_uint4(f2tf(bv.x), f2tf(bv.y), f2tf(bv.z), f2tf(bv.w));
        *(uint4*)(As + r * LDA + c4 * 4) = at4;
        *(uint4*)(Bs + r * LDA + c4 * 4) = bt4;
    }
    __syncthreads();

    float acc[2][8][4] = {};
    mma_core(As, Bs, tid, acc);

    const int lane = tid & 31, wid = tid >> 5;
    const int g = lane >> 2, t = lane & 3;
    const int m0 = (wid & 3) * 32, n0 = (wid >> 2) * 64;

    #pragma unroll
    for (int mf = 0; mf < 2; ++mf) {
        #pragma unroll
        for (int nf = 0; nf < 8; ++nf) {
            int ri = b0 + m0 + 16 * mf + g;
            int e  = e0 + n0 + 8 * nf + 2 * t;
            if (ri < cnt)
                *(float2*)(g_hat + ((size_t)s * B_ + ri) * E_ + e) =
                    make_float2(acc[mf][nf][0], acc[mf][nf][1]);
            if (ri + 8 < cnt)
                *(float2*)(g_hat + ((size_t)s * B_ + ri + 8) * E_ + e) =
                    make_float2(acc[mf][nf][2], acc[mf][nf][3]);
        }
    }
}

// ====================================================================
// K5: routing, 1024 threads, mask-compacted rows via rank map + cp.async
// ====================================================================
#define HPAD 260   // floats per smem row: 16B-aligned cp.async dsts
#define ROUTE_SMEM (S_ * HPAD * 4)   // 208000 B
#define RT_THREADS 1024
__global__ __launch_bounds__(RT_THREADS) void route_kernel(
    const float* __restrict__ mask, float* __restrict__ out_interest)
{
    extern __shared__ float hat_s[];                 // [nact][260]
    __shared__ float cw_s[NI_ * S_];
    __shared__ float sw_s[NI_ * S_];
    __shared__ float cap_s[E_];
    __shared__ float wsum[32];
    __shared__ int   act[S_];
    __shared__ int   act_row[S_];
    __shared__ int   wtot[32];
    __shared__ int   nact_s;

    const int b = blockIdx.x;
    const int tid = threadIdx.x;
    const int lane = tid & 31, wrp = tid >> 5;

    // ---- deterministic compaction of active s (mask != 0) ----
    int pred = (tid < S_) ? (mask[b * S_ + tid] != 0.f) : 0;
    unsigned bal = __ballot_sync(0xffffffffu, pred);
    if (lane == 0) wtot[wrp] = __popc(bal);
    __syncthreads();
    int prefix = 0;
    for (int i = 0; i < wrp && i < 7; ++i) prefix += wtot[i];
    if (pred) act[prefix + __popc(bal & ((1u << lane) - 1u))] = tid;
    if (tid == 0) {
        int t = 0;
        for (int i = 0; i < 7; ++i) t += wtot[i];
        nact_s = t;
    }
    __syncthreads();
    const int nact = nact_s;

    // ---- resolve compacted global row index per active s ----
    for (int c = tid; c < nact; c += RT_THREADS) {
        int s = act[c];
        act_row[c] = s * B_ + g_rank[s * B_ + b];
    }
    for (int x = tid; x < NI_ * S_; x += RT_THREADS) cw_s[x] = 0.f;
    __syncthreads();

    // ---- bulk cp.async load of active hat rows into smem ----
    uint32_t smem_b = (uint32_t)__cvta_generic_to_shared(hat_s);
    for (int x4 = tid; x4 < nact * 64; x4 += RT_THREADS) {
        int c = x4 >> 6, e4 = (x4 & 63) << 2;
        const float* src = g_hat + ((size_t)act_row[c] << 8) + e4;
        CP_ASYNC16(smem_b + (uint32_t)(c * HPAD + e4) * 4, src);
    }
    CP_COMMIT_WAIT();
    __syncthreads();

    const int k = tid >> 8;           // 0..3
    const int d = (tid >> 2) & 63;    // quad shares (k,d)
    const int q = tid & 3;
    const int off = k * 64 + d;
    const int qn = (nact + 3) >> 2;
    float capv = 0.f;

    for (int it = 0; it < 3; ++it) {
        if (tid < nact) {
            float c0 = cw_s[0 * S_ + tid], c1 = cw_s[1 * S_ + tid];
            float c2 = cw_s[2 * S_ + tid], c3 = cw_s[3 * S_ + tid];
            float mx = fmaxf(fmaxf(c0, c1), fmaxf(c2, c3));
            float e0 = __expf(c0 - mx), e1 = __expf(c1 - mx);
            float e2 = __expf(c2 - mx), e3 = __expf(c3 - mx);
            float inv = 1.0f / (e0 + e1 + e2 + e3);
            sw_s[0 * S_ + tid] = e0 * inv;
            sw_s[1 * S_ + tid] = e1 * inv;
            sw_s[2 * S_ + tid] = e2 * inv;
            sw_s[3 * S_ + tid] = e3 * inv;
        }
        __syncthreads();

        // v[k,d] = sum_c sw[k,c]*hat[c, off]; c-range split across quad
        float v = 0.f;
        const float* swk = &sw_s[k * S_];
        const int cbeg = q * qn;
        const int cend = (cbeg + qn < nact) ? cbeg + qn : nact;
        #pragma unroll 4
        for (int c = cbeg; c < cend; ++c)
            v += swk[c] * hat_s[c * HPAD + off];
        v += __shfl_xor_sync(0xffffffffu, v, 1);
        v += __shfl_xor_sync(0xffffffffu, v, 2);     // all 4 hold full sum

        float p = (q == 0) ? v * v : 0.f;
        #pragma unroll
        for (int o = 16; o; o >>= 1) p += __shfl_xor_sync(0xffffffffu, p, o);
        if (lane == 0) wsum[wrp] = p;
        __syncthreads();
        float n = 0.f;
        #pragma unroll
        for (int i = 0; i < 8; ++i) n += wsum[8 * k + i];
        float scale = n / (1.0f + n) / sqrtf(n + 1e-9f);
        capv = scale * v;
        if (q == 0) cap_s[off] = capv;
        __syncthreads();

        if (it < 2) {
            // cw[k,c] += hat[c, kk*64:] . cap[kk,:]   (single pass, <=800 rows)
            int idx = tid;
            if (idx < NI_ * nact) {
                int kk = idx / nact, c = idx - kk * nact;
                const float* hr = &hat_s[c * HPAD + kk * 64];
                const float* cr = &cap_s[kk * 64];
                float dsum = 0.f;
                #pragma unroll 8
                for (int dd = 0; dd < 64; ++dd) dsum += hr[dd] * cr[dd];
                cw_s[kk * S_ + c] += dsum;
            }
            __syncthreads();
        }
    }

    if (q == 0) out_interest[(size_t)b * E_ + off] = capv;
}

// ====================================================================
// launch — critical path (hat->route) on a HIGH-PRIORITY stream;
//          adj overlaps on the default stream.
// ====================================================================
extern "C" void kernel_launch(void* const* d_in, const int* in_sizes, int n_in,
                              void* d_out, int out_size)
{
    const int*   uid      = (const int*)  d_in[0];
    const int*   age      = (const int*)  d_in[1];
    const int*   gender   = (const int*)  d_in[2];
    const int*   occup    = (const int*)  d_in[3];
    const int*   mid_his  = (const int*)  d_in[4];
    const float* mask     = (const float*)d_in[5];
    const float* ue       = (const float*)d_in[6];
    const float* at       = (const float*)d_in[7];
    const float* gt       = (const float*)d_in[8];
    const float* ot       = (const float*)d_in[9];
    const float* mid_emb  = (const float*)d_in[10];
    const float* w        = (const float*)d_in[11];
    float* out = (float*)d_out;

    static cudaStream_t s2 = nullptr;
    static cudaEvent_t ev_fork = nullptr, ev_join = nullptr;
    if (!s2) {
        int lo, hi;
        cudaDeviceGetStreamPriorityRange(&lo, &hi);
        cudaStreamCreateWithPriority(&s2, cudaStreamNonBlocking, hi);
        cudaEventCreateWithFlags(&ev_fork, cudaEventDisableTiming);
        cudaEventCreateWithFlags(&ev_join, cudaEventDisableTiming);
        cudaFuncSetAttribute(route_kernel,
                             cudaFuncAttributeMaxDynamicSharedMemorySize, ROUTE_SMEM);
        cudaFuncSetAttribute(adj_kernel,
                             cudaFuncAttributeMaxDynamicSharedMemorySize, SMEM_GEMM_BYTES);
        cudaFuncSetAttribute(hat_kernel,
                             cudaFuncAttributeMaxDynamicSharedMemorySize, SMEM_GEMM_BYTES);
    }

    uprof_kernel<<<B_ * D_ / 256, 256>>>(uid, age, gender, occup, ue, at, gt, ot);
    gather_kernel<<<B_ * S_ * 16 / 256, 256>>>(mid_his, mask, mid_emb);

    cudaEventRecord(ev_fork, 0);
    cudaStreamWaitEvent(s2, ev_fork, 0);

    hat_kernel<<<dim3(2, B_ / 128, S_), 256, SMEM_GEMM_BYTES, s2>>>(w);
    route_kernel<<<B_, RT_THREADS, ROUTE_SMEM, s2>>>(mask, out);

    adj_kernel<<<dim3(2, 2, B_), 256, SMEM_GEMM_BYTES>>>(mask, out + INTEREST_ELEMS);

    cudaEventRecord(ev_join, s2);
    cudaStreamWaitEvent(0, ev_join, 0);
}

// round 11
// speedup vs baseline: 1.0064x; 1.0064x over previous
#include <cuda_runtime.h>
#include <cstdint>

// ---------------- problem constants ----------------
#define B_   1024
#define S_   200
#define D_   64
#define NI_  4
#define E_   256            // NI * D
#define INTEREST_ELEMS (B_ * NI_ * D_)   // 262144, adj follows at this offset

// ---------------- device scratch (static; no runtime alloc) ----------------
__device__ float g_uprof[B_ * D_];                       // 256 KB
__device__ float g_item[(long long)B_ * S_ * D_];        // 52.4 MB
__device__ float g_hat [(long long)S_ * B_ * E_];        // 209.7 MB, [s][rank][e]
__device__ int   g_cnt [S_];                             // active-b count per s
__device__ int   g_blist[S_ * B_];                       // [s][rank] -> b
__device__ int   g_rank [S_ * B_];                       // [s][b] -> rank

// ---------------- async-copy helpers ----------------
#define CP_BULK(dst_u32, src_ptr, bytes, mbar_u32) \
    asm volatile("cp.async.bulk.shared::cta.global.mbarrier::complete_tx::bytes " \
                 "[%0], [%1], %2, [%3];" \
                 :: "r"(dst_u32), "l"(src_ptr), "r"(bytes), "r"(mbar_u32) : "memory")
#define MBAR_INIT(mbar_u32, cnt) \
    asm volatile("mbarrier.init.shared.b64 [%0], %1;" :: "r"(mbar_u32), "r"(cnt) : "memory")
#define MBAR_EXPECT_TX(mbar_u32, bytes) \
    asm volatile("mbarrier.arrive.expect_tx.shared.b64 _, [%0], %1;" \
                 :: "r"(mbar_u32), "r"(bytes) : "memory")
#define MBAR_WAIT(mbar_u32, parity) do { \
    asm volatile( \
        "{\n\t.reg .pred P1;\n\t" \
        "WAIT_LOOP_%=:\n\t" \
        "mbarrier.try_wait.parity.shared.b64 P1, [%0], %1;\n\t" \
        "@P1 bra.uni WAIT_DONE_%=;\n\t" \
        "bra.uni WAIT_LOOP_%=;\n\t" \
        "WAIT_DONE_%=:\n\t}" \
        :: "r"(mbar_u32), "r"(parity) : "memory"); \
} while (0)

// ---------------- tf32 mma helpers ----------------
__device__ __forceinline__ uint32_t f2tf(float x) {
    uint32_t u;
    asm("cvt.rna.tf32.f32 %0, %1;" : "=r"(u) : "f"(x));
    return u;
}

__device__ __forceinline__ void mma8(float* d, const uint32_t* a,
                                     uint32_t b0, uint32_t b1) {
    asm volatile(
        "mma.sync.aligned.m16n8k8.row.col.f32.tf32.tf32.f32 "
        "{%0,%1,%2,%3}, {%4,%5,%6,%7}, {%8,%9}, {%0,%1,%2,%3};"
        : "+f"(d[0]), "+f"(d[1]), "+f"(d[2]), "+f"(d[3])
        : "r"(a[0]), "r"(a[1]), "r"(a[2]), "r"(a[3]), "r"(b0), "r"(b1));
}

#define LDA 68     // smem row stride (uint32); conflict-free fragment LDS
#define SMEM_GEMM_BYTES (2 * 128 * LDA * 4)   // 69632

// 128x128x64 block tile, 8 warps of 32x64 each.
__device__ __forceinline__ void mma_core(const uint32_t* __restrict__ As,
                                         const uint32_t* __restrict__ Bs,
                                         int tid, float acc[2][8][4]) {
    const int lane = tid & 31, wid = tid >> 5;
    const int g = lane >> 2, t = lane & 3;
    const int m0 = (wid & 3) * 32, n0 = (wid >> 2) * 64;
    #pragma unroll
    for (int k0 = 0; k0 < 64; k0 += 8) {
        uint32_t a[2][4];
        #pragma unroll
        for (int mf = 0; mf < 2; ++mf) {
            const uint32_t* p = As + (m0 + 16 * mf + g) * LDA + k0 + t;
            a[mf][0] = p[0];
            a[mf][1] = p[8 * LDA];
            a[mf][2] = p[4];
            a[mf][3] = p[8 * LDA + 4];
        }
        #pragma unroll
        for (int nf = 0; nf < 8; ++nf) {
            const uint32_t* p = Bs + (n0 + 8 * nf + g) * LDA + k0 + t;
            uint32_t b0v = p[0], b1v = p[4];
            mma8(acc[0][nf], a[0], b0v, b1v);
            mma8(acc[1][nf], a[1], b0v, b1v);
        }
    }
}

// ====================================================================
// K1: user profile (+ zero the per-s active counters)
// ====================================================================
__global__ __launch_bounds__(256) void uprof_kernel(
    const int* __restrict__ uid, const int* __restrict__ age,
    const int* __restrict__ gender, const int* __restrict__ occup,
    const float* __restrict__ ue, const float* __restrict__ at,
    const float* __restrict__ gt, const float* __restrict__ ot)
{
    if (blockIdx.x == 0 && threadIdx.x < S_) g_cnt[threadIdx.x] = 0;
    int idx = blockIdx.x * 256 + threadIdx.x;
    int b = idx >> 6, d = idx & 63;
    float v = ue[(size_t)uid[b]    * 64 + d]
            + gt[(size_t)gender[b] * 64 + d]
            + at[(size_t)age[b]    * 64 + d]
            + ot[(size_t)occup[b]  * 64 + d];
    g_uprof[idx] = 0.25f * v;
}

// ====================================================================
// K2: item_his = mid_emb[mid_his]*mask  (+ build per-s active-b lists)
// ====================================================================
__global__ __launch_bounds__(256) void gather_kernel(
    const int* __restrict__ mid_his, const float* __restrict__ mask,
    const float* __restrict__ mid_emb)
{
    int t  = blockIdx.x * 256 + threadIdx.x;
    int bs = t >> 4, q = t & 15;
    int mi = mid_his[bs];
    float m = mask[bs];
    float4 e = ((const float4*)mid_emb)[(size_t)mi * 16 + q];
    float4 it;
    it.x = e.x * m;  it.y = e.y * m;  it.z = e.z * m;  it.w = e.w * m;
    ((float4*)g_item)[(size_t)bs * 16 + q] = it;

    if (q == 0 && m != 0.f) {
        int b = bs / S_, s = bs - b * S_;
        int r = atomicAdd(&g_cnt[s], 1);
        g_blist[s * B_ + r] = b;
        g_rank [s * B_ + b] = r;
    }
}

// ====================================================================
// K3: adj — tf32 tensor cores, tile 128x128, grid (2,2,B)
// ====================================================================
__global__ __launch_bounds__(256) void adj_kernel(
    const float* __restrict__ mask, float* __restrict__ out)
{
    extern __shared__ uint32_t sh[];
    uint32_t* As = sh;
    uint32_t* Bs = sh + 128 * LDA;
    __shared__ float msk[256];

    const int b  = blockIdx.z;
    const int i0 = blockIdx.y * 128;
    const int j0 = blockIdx.x * 128;
    const int tid = threadIdx.x;
    const float* It = g_item + (size_t)b * (S_ * D_);

    msk[tid] = (tid < S_) ? mask[b * S_ + tid] : 0.f;

    #pragma unroll
    for (int p = 0; p < 8; ++p) {
        int q = tid + p * 256;
        int r = q >> 4, c4 = q & 15;
        float4 up = ((const float4*)g_uprof)[b * 16 + c4];
        float4 av = make_float4(0.f, 0.f, 0.f, 0.f);
        float4 bv = make_float4(0.f, 0.f, 0.f, 0.f);
        if (i0 + r < S_) {
            float4 iv = *(const float4*)(It + (size_t)(i0 + r) * 64 + c4 * 4);
            av.x = iv.x * up.x; av.y = iv.y * up.y;
            av.z = iv.z * up.z; av.w = iv.w * up.w;
        }
        if (j0 + r < S_) bv = *(const float4*)(It + (size_t)(j0 + r) * 64 + c4 * 4);
        uint4 at4 = make_uint4(f2tf(av.x), f2tf(av.y), f2tf(av.z), f2tf(av.w));
        uint4 bt4 = make_uint4(f2tf(bv.x), f2tf(bv.y), f2tf(bv.z), f2tf(bv.w));
        *(uint4*)(As + r * LDA + c4 * 4) = at4;
        *(uint4*)(Bs + r * LDA + c4 * 4) = bt4;
    }
    __syncthreads();

    float acc[2][8][4] = {};
    mma_core(As, Bs, tid, acc);

    const int lane = tid & 31, wid = tid >> 5;
    const int g = lane >> 2, t = lane & 3;
    const int m0 = (wid & 3) * 32, n0 = (wid >> 2) * 64;
    float* outb = out + (size_t)b * (S_ * S_);

    #pragma unroll
    for (int mf = 0; mf < 2; ++mf) {
        #pragma unroll
        for (int nf = 0; nf < 8; ++nf) {
            int i = i0 + m0 + 16 * mf + g;
            int j = j0 + n0 + 8 * nf + 2 * t;
            if (j < S_) {
                float mj0 = msk[j], mj1 = msk[j + 1];
                if (i < S_) {
                    float mi = msk[i];
                    float s0 = 1.f / (1.f + __expf(-acc[mf][nf][0]));
                    float s1 = 1.f / (1.f + __expf(-acc[mf][nf][1]));
                    *(float2*)(outb + (size_t)i * S_ + j) =
                        make_float2(s0 * mi * mj0, s1 * mi * mj1);
                }
                if (i + 8 < S_) {
                    float mi = msk[i + 8];
                    float s2 = 1.f / (1.f + __expf(-acc[mf][nf][2]));
                    float s3 = 1.f / (1.f + __expf(-acc[mf][nf][3]));
                    *(float2*)(outb + (size_t)(i + 8) * S_ + j) =
                        make_float2(s2 * mi * mj0, s3 * mi * mj1);
                }
            }
        }
    }
}

// ====================================================================
// K4: hat — tf32 tensor cores, ACTIVE b-rows only, compacted output.
// ====================================================================
__global__ __launch_bounds__(256) void hat_kernel(const float* __restrict__ w)
{
    const int s   = blockIdx.z;
    const int cnt = g_cnt[s];
    const int b0  = blockIdx.y * 128;
    if (b0 >= cnt) return;
    const int e0  = blockIdx.x * 128;
    const int tid = threadIdx.x;

    extern __shared__ uint32_t sh[];
    uint32_t* As = sh;
    uint32_t* Bs = sh + 128 * LDA;

    #pragma unroll
    for (int p = 0; p < 8; ++p) {
        int q = tid + p * 256;
        int r = q >> 4, c4 = q & 15;
        float4 av = make_float4(0.f, 0.f, 0.f, 0.f);
        if (b0 + r < cnt) {
            int bidx = g_blist[s * B_ + b0 + r];
            av = *(const float4*)(g_item + ((size_t)bidx * S_ + s) * 64 + c4 * 4);
        }
        float4 bv = *(const float4*)(w + ((size_t)s * E_ + (e0 + r)) * 64 + c4 * 4);
        uint4 at4 = make_uint4(f2tf(av.x), f2tf(av.y), f2tf(av.z), f2tf(av.w));
        uint4 bt4 = make_uint4(f2tf(bv.x), f2tf(bv.y), f2tf(bv.z), f2tf(bv.w));
        *(uint4*)(As + r * LDA + c4 * 4) = at4;
        *(uint4*)(Bs + r * LDA + c4 * 4) = bt4;
    }
    __syncthreads();

    float acc[2][8][4] = {};
    mma_core(As, Bs, tid, acc);

    const int lane = tid & 31, wid = tid >> 5;
    const int g = lane >> 2, t = lane & 3;
    const int m0 = (wid & 3) * 32, n0 = (wid >> 2) * 64;

    #pragma unroll
    for (int mf = 0; mf < 2; ++mf) {
        #pragma unroll
        for (int nf = 0; nf < 8; ++nf) {
            int ri = b0 + m0 + 16 * mf + g;
            int e  = e0 + n0 + 8 * nf + 2 * t;
            if (ri < cnt)
                *(float2*)(g_hat + ((size_t)s * B_ + ri) * E_ + e) =
                    make_float2(acc[mf][nf][0], acc[mf][nf][1]);
            if (ri + 8 < cnt)
                *(float2*)(g_hat + ((size_t)s * B_ + ri + 8) * E_ + e) =
                    make_float2(acc[mf][nf][2], acc[mf][nf][3]);
        }
    }
}

// ====================================================================
// K5: routing, 512 threads; active rows loaded via cp.async.bulk
//     (1 op per 1KB row) + mbarrier; conflict-free cw-update.
// ====================================================================
#define HPAD 260   // floats per smem row (1040 B, 16B multiple)
#define ROUTE_SMEM (S_ * HPAD * 4)   // 208000 B
#define RT_THREADS 512
__global__ __launch_bounds__(RT_THREADS) void route_kernel(
    const float* __restrict__ mask, float* __restrict__ out_interest)
{
    extern __shared__ float hat_s[];                 // [nact][260]
    __shared__ float cw_s[NI_ * S_];
    __shared__ float sw_s[NI_ * S_];
    __shared__ float cap_s[E_];
    __shared__ float wsum[16];
    __shared__ int   act[S_];
    __shared__ int   act_row[S_];
    __shared__ int   wtot[16];
    __shared__ int   nact_s;
    __shared__ __align__(8) uint64_t mbar;

    const int b = blockIdx.x;
    const int tid = threadIdx.x;
    const int lane = tid & 31, wrp = tid >> 5;
    const uint32_t mbar_u32 = (uint32_t)__cvta_generic_to_shared(&mbar);

    // ---- deterministic compaction of active s (mask != 0) ----
    int pred = (tid < S_) ? (mask[b * S_ + tid] != 0.f) : 0;
    unsigned bal = __ballot_sync(0xffffffffu, pred);
    if (lane == 0) wtot[wrp] = __popc(bal);
    if (tid == 0) MBAR_INIT(mbar_u32, 1);
    __syncthreads();
    int prefix = 0;
    for (int i = 0; i < wrp && i < 7; ++i) prefix += wtot[i];
    if (pred) act[prefix + __popc(bal & ((1u << lane) - 1u))] = tid;
    if (tid == 0) {
        int t = 0;
        for (int i = 0; i < 7; ++i) t += wtot[i];
        nact_s = t;
    }
    __syncthreads();
    const int nact = nact_s;

    // ---- resolve compacted global row index per active s ----
    if (tid < nact) {
        int s = act[tid];
        act_row[tid] = s * B_ + g_rank[s * B_ + b];
    }
    for (int x = tid; x < NI_ * S_; x += RT_THREADS) cw_s[x] = 0.f;
    __syncthreads();

    // ---- bulk-async load: one 1KB cp.async.bulk per active row ----
    uint32_t smem_b = (uint32_t)__cvta_generic_to_shared(hat_s);
    if (tid == 0) MBAR_EXPECT_TX(mbar_u32, (uint32_t)(nact * E_ * 4));
    __syncthreads();
    if (tid < nact) {
        const float* src = g_hat + ((size_t)act_row[tid] << 8);
        CP_BULK(smem_b + (uint32_t)(tid * HPAD) * 4, src, E_ * 4, mbar_u32);
    }
    MBAR_WAIT(mbar_u32, 0);
    __syncthreads();

    const int k = tid >> 7;           // 0..3
    const int d = (tid >> 1) & 63;    // pair shares (k,d)
    const int half = tid & 1;
    const int off = k * 64 + d;
    const int hn = (nact + 1) >> 1;
    const int g8 = lane >> 2, q4 = lane & 3;     // cw-update layout
    float capv = 0.f;

    for (int it = 0; it < 3; ++it) {
        if (tid < nact) {
            float c0 = cw_s[0 * S_ + tid], c1 = cw_s[1 * S_ + tid];
            float c2 = cw_s[2 * S_ + tid], c3 = cw_s[3 * S_ + tid];
            float mx = fmaxf(fmaxf(c0, c1), fmaxf(c2, c3));
            float e0 = __expf(c0 - mx), e1 = __expf(c1 - mx);
            float e2 = __expf(c2 - mx), e3 = __expf(c3 - mx);
            float inv = 1.0f / (e0 + e1 + e2 + e3);
            sw_s[0 * S_ + tid] = e0 * inv;
            sw_s[1 * S_ + tid] = e1 * inv;
            sw_s[2 * S_ + tid] = e2 * inv;
            sw_s[3 * S_ + tid] = e3 * inv;
        }
        __syncthreads();

        // v[k,d] = sum_c sw[k,c]*hat[c, off]; c-range split across pair
        float v = 0.f;
        const float* swk = &sw_s[k * S_];
        const int cbeg = half * hn;
        const int cend = (cbeg + hn < nact) ? cbeg + hn : nact;
        #pragma unroll 4
        for (int c = cbeg; c < cend; ++c)
            v += swk[c] * hat_s[c * HPAD + off];
        v += __shfl_xor_sync(0xffffffffu, v, 1);     // both halves: full sum

        float p = half ? 0.f : v * v;
        #pragma unroll
        for (int o = 16; o; o >>= 1) p += __shfl_xor_sync(0xffffffffu, p, o);
        if (lane == 0) wsum[wrp] = p;
        __syncthreads();
        float n = wsum[4 * k] + wsum[4 * k + 1] + wsum[4 * k + 2] + wsum[4 * k + 3];
        float scale = n / (1.0f + n) / sqrtf(n + 1e-9f);
        capv = scale * v;
        if (!half) cap_s[off] = capv;
        __syncthreads();

        if (it < 2) {
            // cw[kk,c] += hat[c, kk*64:] . cap[kk,:]
            // 4 lanes per dot (q4), lane sums dd = q4 + 4i -> banks 4g8+q4,
            // all 32 distinct: conflict-free.
            const int ndots = NI_ * nact;
            for (int j0 = wrp * 8; j0 < ndots; j0 += 16 * 8) {
                int j = j0 + g8;
                float p2 = 0.f;
                int kk = 0, c = 0;
                if (j < ndots) {
                    kk = j / nact; c = j - kk * nact;
                    const float* hr = &hat_s[c * HPAD + kk * 64 + q4];
                    const float* cr = &cap_s[kk * 64 + q4];
                    #pragma unroll
                    for (int i = 0; i < 16; ++i)
                        p2 += hr[4 * i] * cr[4 * i];
                }
                p2 += __shfl_xor_sync(0xffffffffu, p2, 1);
                p2 += __shfl_xor_sync(0xffffffffu, p2, 2);
                if (j < ndots && q4 == 0) cw_s[kk * S_ + c] += p2;
            }
            __syncthreads();
        }
    }

    if (!half) out_interest[(size_t)b * E_ + off] = capv;
}

// ====================================================================
// launch — critical path (hat->route) on a HIGH-PRIORITY stream;
//          adj overlaps on the default stream.
// ====================================================================
extern "C" void kernel_launch(void* const* d_in, const int* in_sizes, int n_in,
                              void* d_out, int out_size)
{
    const int*   uid      = (const int*)  d_in[0];
    const int*   age      = (const int*)  d_in[1];
    const int*   gender   = (const int*)  d_in[2];
    const int*   occup    = (const int*)  d_in[3];
    const int*   mid_his  = (const int*)  d_in[4];
    const float* mask     = (const float*)d_in[5];
    const float* ue       = (const float*)d_in[6];
    const float* at       = (const float*)d_in[7];
    const float* gt       = (const float*)d_in[8];
    const float* ot       = (const float*)d_in[9];
    const float* mid_emb  = (const float*)d_in[10];
    const float* w        = (const float*)d_in[11];
    float* out = (float*)d_out;

    static cudaStream_t s2 = nullptr;
    static cudaEvent_t ev_fork = nullptr, ev_join = nullptr;
    if (!s2) {
        int lo, hi;
        cudaDeviceGetStreamPriorityRange(&lo, &hi);
        cudaStreamCreateWithPriority(&s2, cudaStreamNonBlocking, hi);
        cudaEventCreateWithFlags(&ev_fork, cudaEventDisableTiming);
        cudaEventCreateWithFlags(&ev_join, cudaEventDisableTiming);
        cudaFuncSetAttribute(route_kernel,
                             cudaFuncAttributeMaxDynamicSharedMemorySize, ROUTE_SMEM);
        cudaFuncSetAttribute(adj_kernel,
                             cudaFuncAttributeMaxDynamicSharedMemorySize, SMEM_GEMM_BYTES);
        cudaFuncSetAttribute(hat_kernel,
                             cudaFuncAttributeMaxDynamicSharedMemorySize, SMEM_GEMM_BYTES);
    }

    uprof_kernel<<<B_ * D_ / 256, 256>>>(uid, age, gender, occup, ue, at, gt, ot);
    gather_kernel<<<B_ * S_ * 16 / 256, 256>>>(mid_his, mask, mid_emb);

    cudaEventRecord(ev_fork, 0);
    cudaStreamWaitEvent(s2, ev_fork, 0);

    hat_kernel<<<dim3(2, B_ / 128, S_), 256, SMEM_GEMM_BYTES, s2>>>(w);
    route_kernel<<<B_, RT_THREADS, ROUTE_SMEM, s2>>>(mask, out);

    adj_kernel<<<dim3(2, 2, B_), 256, SMEM_GEMM_BYTES>>>(mask, out + INTEREST_ELEMS);

    cudaEventRecord(ev_join, s2);
    cudaStreamWaitEvent(0, ev_join, 0);
}

// round 12
// speedup vs baseline: 1.0972x; 1.0902x over previous
#include <cuda_runtime.h>
#include <cstdint>

// ---------------- problem constants ----------------
#define B_   1024
#define S_   200
#define D_   64
#define NI_  4
#define E_   256            // NI * D
#define INTEREST_ELEMS (B_ * NI_ * D_)   // 262144, adj follows at this offset

// ---------------- device scratch (static; no runtime alloc) ----------------
__device__ float g_uprof[B_ * D_];                       // 256 KB
__device__ float g_item[(long long)B_ * S_ * D_];        // 52.4 MB
__device__ float g_hat [(long long)S_ * B_ * E_];        // 209.7 MB, [s][rank][e]
__device__ int   g_cnt [S_];                             // active-b count per s
__device__ int   g_blist[S_ * B_];                       // [s][rank] -> b
__device__ int   g_rank [S_ * B_];                       // [s][b] -> rank

// ---------------- cp.async helpers ----------------
#define CP_ASYNC16(dst_u32, src_ptr) \
    asm volatile("cp.async.cg.shared.global [%0], [%1], 16;" \
                 :: "r"(dst_u32), "l"(src_ptr))
#define CP_COMMIT_WAIT() \
    asm volatile("cp.async.commit_group;\ncp.async.wait_group 0;" ::: "memory")

// ---------------- tf32 mma helpers ----------------
__device__ __forceinline__ uint32_t f2tf(float x) {
    uint32_t u;
    asm("cvt.rna.tf32.f32 %0, %1;" : "=r"(u) : "f"(x));
    return u;
}

__device__ __forceinline__ void mma8(float* d, const uint32_t* a,
                                     uint32_t b0, uint32_t b1) {
    asm volatile(
        "mma.sync.aligned.m16n8k8.row.col.f32.tf32.tf32.f32 "
        "{%0,%1,%2,%3}, {%4,%5,%6,%7}, {%8,%9}, {%0,%1,%2,%3};"
        : "+f"(d[0]), "+f"(d[1]), "+f"(d[2]), "+f"(d[3])
        : "r"(a[0]), "r"(a[1]), "r"(a[2]), "r"(a[3]), "r"(b0), "r"(b1));
}

#define LDA 68     // smem row stride (uint32); conflict-free fragment LDS
#define SMEM_GEMM_BYTES (2 * 128 * LDA * 4)   // 69632

// 128x128x64 block tile, 8 warps of 32x64 each.
__device__ __forceinline__ void mma_core(const uint32_t* __restrict__ As,
                                         const uint32_t* __restrict__ Bs,
                                         int tid, float acc[2][8][4]) {
    const int lane = tid & 31, wid = tid >> 5;
    const int g = lane >> 2, t = lane & 3;
    const int m0 = (wid & 3) * 32, n0 = (wid >> 2) * 64;
    #pragma unroll
    for (int k0 = 0; k0 < 64; k0 += 8) {
        uint32_t a[2][4];
        #pragma unroll
        for (int mf = 0; mf < 2; ++mf) {
            const uint32_t* p = As + (m0 + 16 * mf + g) * LDA + k0 + t;
            a[mf][0] = p[0];
            a[mf][1] = p[8 * LDA];
            a[mf][2] = p[4];
            a[mf][3] = p[8 * LDA + 4];
        }
        #pragma unroll
        for (int nf = 0; nf < 8; ++nf) {
            const uint32_t* p = Bs + (n0 + 8 * nf + g) * LDA + k0 + t;
            uint32_t b0v = p[0], b1v = p[4];
            mma8(acc[0][nf], a[0], b0v, b1v);
            mma8(acc[1][nf], a[1], b0v, b1v);
        }
    }
}

// ====================================================================
// K1: user profile (+ zero the per-s active counters)
// ====================================================================
__global__ __launch_bounds__(256) void uprof_kernel(
    const int* __restrict__ uid, const int* __restrict__ age,
    const int* __restrict__ gender, const int* __restrict__ occup,
    const float* __restrict__ ue, const float* __restrict__ at,
    const float* __restrict__ gt, const float* __restrict__ ot)
{
    if (blockIdx.x == 0 && threadIdx.x < S_) g_cnt[threadIdx.x] = 0;
    int idx = blockIdx.x * 256 + threadIdx.x;
    int b = idx >> 6, d = idx & 63;
    float v = ue[(size_t)uid[b]    * 64 + d]
            + gt[(size_t)gender[b] * 64 + d]
            + at[(size_t)age[b]    * 64 + d]
            + ot[(size_t)occup[b]  * 64 + d];
    g_uprof[idx] = 0.25f * v;
}

// ====================================================================
// K2: item_his = mid_emb[mid_his]*mask  (+ build per-s active-b lists)
// ====================================================================
__global__ __launch_bounds__(256) void gather_kernel(
    const int* __restrict__ mid_his, const float* __restrict__ mask,
    const float* __restrict__ mid_emb)
{
    int t  = blockIdx.x * 256 + threadIdx.x;
    int bs = t >> 4, q = t & 15;
    int mi = mid_his[bs];
    float m = mask[bs];
    float4 e = ((const float4*)mid_emb)[(size_t)mi * 16 + q];
    float4 it;
    it.x = e.x * m;  it.y = e.y * m;  it.z = e.z * m;  it.w = e.w * m;
    ((float4*)g_item)[(size_t)bs * 16 + q] = it;

    if (q == 0 && m != 0.f) {
        int b = bs / S_, s = bs - b * S_;
        int r = atomicAdd(&g_cnt[s], 1);
        g_blist[s * B_ + r] = b;
        g_rank [s * B_ + b] = r;
    }
}

// ====================================================================
// K3: adj — tf32 tensor cores, ROW-COMPACTED (active i only; ~2x fewer
//     MMA blocks). y=1 blocks zero-fill the inactive (all-zero) rows.
//     Active rows have m_i = 1.0 -> surviving values bit-identical.
// ====================================================================
__global__ __launch_bounds__(256) void adj_kernel(
    const float* __restrict__ mask, float* __restrict__ out)
{
    extern __shared__ uint32_t sh[];
    uint32_t* As = sh;
    uint32_t* Bs = sh + 128 * LDA;
    __shared__ float msk[256];
    __shared__ int act[S_], inact[S_];
    __shared__ int wtotA[8], wtotI[8];
    __shared__ int nact_s;

    const int b  = blockIdx.z;
    const int i0 = blockIdx.y * 128;       // compacted-row tile origin
    const int j0 = blockIdx.x * 128;
    const int tid = threadIdx.x;
    const int lane = tid & 31, wrp = tid >> 5;
    const float* It = g_item + (size_t)b * (S_ * D_);
    float* outb = out + (size_t)b * (S_ * S_);

    float mval = (tid < S_) ? mask[b * S_ + tid] : 0.f;
    msk[tid] = mval;

    // ---- deterministic compaction: active rows & inactive rows ----
    int predA = (tid < S_) && (mval != 0.f);
    int predI = (tid < S_) && (mval == 0.f);
    unsigned balA = __ballot_sync(0xffffffffu, predA);
    unsigned balI = __ballot_sync(0xffffffffu, predI);
    if (lane == 0) { wtotA[wrp] = __popc(balA); wtotI[wrp] = __popc(balI); }
    __syncthreads();
    int pA = 0, pI = 0;
    for (int i = 0; i < wrp; ++i) { pA += wtotA[i]; pI += wtotI[i]; }
    unsigned ltm = (1u << lane) - 1u;
    if (predA) act[pA + __popc(balA & ltm)] = tid;
    if (predI) inact[pI + __popc(balI & ltm)] = tid;
    if (tid == 0) {
        int t = 0;
        for (int i = 0; i < 7; ++i) t += wtotA[i];
        nact_s = t;
    }
    __syncthreads();
    const int nact = nact_s;

    // ---- y=1 blocks: zero-fill inactive rows for this j-range ----
    if (blockIdx.y == 1) {
        int ninact = S_ - nact;
        int jw = (j0 + 128 <= S_) ? 128 : (S_ - j0);   // 128 or 72
        int nf4 = jw >> 2;
        for (int x = tid; x < ninact * nf4; x += 256) {
            int r = x / nf4, c4 = x - r * nf4;
            *(float4*)(outb + (size_t)inact[r] * S_ + j0 + c4 * 4) =
                make_float4(0.f, 0.f, 0.f, 0.f);
        }
    }
    if (i0 >= nact) return;

    // ---- tile fill: A rows gathered via act[] (x uprof), B dense ----
    #pragma unroll
    for (int p = 0; p < 8; ++p) {
        int q = tid + p * 256;
        int r = q >> 4, c4 = q & 15;
        float4 up = ((const float4*)g_uprof)[b * 16 + c4];
        float4 av = make_float4(0.f, 0.f, 0.f, 0.f);
        float4 bv = make_float4(0.f, 0.f, 0.f, 0.f);
        if (i0 + r < nact) {
            float4 iv = *(const float4*)(It + (size_t)act[i0 + r] * 64 + c4 * 4);
            av.x = iv.x * up.x; av.y = iv.y * up.y;
            av.z = iv.z * up.z; av.w = iv.w * up.w;
        }
        if (j0 + r < S_) bv = *(const float4*)(It + (size_t)(j0 + r) * 64 + c4 * 4);
        uint4 at4 = make_uint4(f2tf(av.x), f2tf(av.y), f2tf(av.z), f2tf(av.w));
        uint4 bt4 = make_uint4(f2tf(bv.x), f2tf(bv.y), f2tf(bv.z), f2tf(bv.w));
        *(uint4*)(As + r * LDA + c4 * 4) = at4;
        *(uint4*)(Bs + r * LDA + c4 * 4) = bt4;
    }
    __syncthreads();

    float acc[2][8][4] = {};
    mma_core(As, Bs, tid, acc);

    const int g = lane >> 2, t = lane & 3;
    const int wid = tid >> 5;
    const int m0 = (wid & 3) * 32, n0 = (wid >> 2) * 64;

    #pragma unroll
    for (int mf = 0; mf < 2; ++mf) {
        #pragma unroll
        for (int nf = 0; nf < 8; ++nf) {
            int ci = i0 + m0 + 16 * mf + g;          // compacted row idx
            int j  = j0 + n0 + 8 * nf + 2 * t;
            if (j < S_) {
                float mj0 = msk[j], mj1 = msk[j + 1];
                if (ci < nact) {
                    int i = act[ci];                 // m_i == 1
                    float s0 = 1.f / (1.f + __expf(-acc[mf][nf][0]));
                    float s1 = 1.f / (1.f + __expf(-acc[mf][nf][1]));
                    *(float2*)(outb + (size_t)i * S_ + j) =
                        make_float2(s0 * mj0, s1 * mj1);
                }
                if (ci + 8 < nact) {
                    int i = act[ci + 8];
                    float s2 = 1.f / (1.f + __expf(-acc[mf][nf][2]));
                    float s3 = 1.f / (1.f + __expf(-acc[mf][nf][3]));
                    *(float2*)(outb + (size_t)i * S_ + j) =
                        make_float2(s2 * mj0, s3 * mj1);
                }
            }
        }
    }
}

// ====================================================================
// K4: hat — tf32 tensor cores, ACTIVE b-rows only, compacted output.
// ====================================================================
__global__ __launch_bounds__(256) void hat_kernel(const float* __restrict__ w)
{
    const int s   = blockIdx.z;
    const int cnt = g_cnt[s];
    const int b0  = blockIdx.y * 128;
    if (b0 >= cnt) return;
    const int e0  = blockIdx.x * 128;
    const int tid = threadIdx.x;

    extern __shared__ uint32_t sh[];
    uint32_t* As = sh;
    uint32_t* Bs = sh + 128 * LDA;

    #pragma unroll
    for (int p = 0; p < 8; ++p) {
        int q = tid + p * 256;
        int r = q >> 4, c4 = q & 15;
        float4 av = make_float4(0.f, 0.f, 0.f, 0.f);
        if (b0 + r < cnt) {
            int bidx = g_blist[s * B_ + b0 + r];
            av = *(const float4*)(g_item + ((size_t)bidx * S_ + s) * 64 + c4 * 4);
        }
        float4 bv = *(const float4*)(w + ((size_t)s * E_ + (e0 + r)) * 64 + c4 * 4);
        uint4 at4 = make_uint4(f2tf(av.x), f2tf(av.y), f2tf(av.z), f2tf(av.w));
        uint4 bt4 = make_uint4(f2tf(bv.x), f2tf(bv.y), f2tf(bv.z), f2tf(bv.w));
        *(uint4*)(As + r * LDA + c4 * 4) = at4;
        *(uint4*)(Bs + r * LDA + c4 * 4) = bt4;
    }
    __syncthreads();

    float acc[2][8][4] = {};
    mma_core(As, Bs, tid, acc);

    const int lane = tid & 31, wid = tid >> 5;
    const int g = lane >> 2, t = lane & 3;
    const int m0 = (wid & 3) * 32, n0 = (wid >> 2) * 64;

    #pragma unroll
    for (int mf = 0; mf < 2; ++mf) {
        #pragma unroll
        for (int nf = 0; nf < 8; ++nf) {
            int ri = b0 + m0 + 16 * mf + g;
            int e  = e0 + n0 + 8 * nf + 2 * t;
            if (ri < cnt)
                *(float2*)(g_hat + ((size_t)s * B_ + ri) * E_ + e) =
                    make_float2(acc[mf][nf][0], acc[mf][nf][1]);
            if (ri + 8 < cnt)
                *(float2*)(g_hat + ((size_t)s * B_ + ri + 8) * E_ + e) =
                    make_float2(acc[mf][nf][2], acc[mf][nf][3]);
        }
    }
}

// ====================================================================
// K5: routing, 512 threads; R8 loader (cp.async.cg 16B, measured best)
//     + conflict-free cw-update.
// ====================================================================
#define HPAD 260   // floats per smem row (1040 B, 16B multiple)
#define ROUTE_SMEM (S_ * HPAD * 4)   // 208000 B
#define RT_THREADS 512
__global__ __launch_bounds__(RT_THREADS) void route_kernel(
    const float* __restrict__ mask, float* __restrict__ out_interest)
{
    extern __shared__ float hat_s[];                 // [nact][260]
    __shared__ float cw_s[NI_ * S_];
    __shared__ float sw_s[NI_ * S_];
    __shared__ float cap_s[E_];
    __shared__ float wsum[16];
    __shared__ int   act[S_];
    __shared__ int   act_row[S_];
    __shared__ int   wtot[16];
    __shared__ int   nact_s;

    const int b = blockIdx.x;
    const int tid = threadIdx.x;
    const int lane = tid & 31, wrp = tid >> 5;

    // ---- deterministic compaction of active s (mask != 0) ----
    int pred = (tid < S_) ? (mask[b * S_ + tid] != 0.f) : 0;
    unsigned bal = __ballot_sync(0xffffffffu, pred);
    if (lane == 0) wtot[wrp] = __popc(bal);
    __syncthreads();
    int prefix = 0;
    for (int i = 0; i < wrp && i < 7; ++i) prefix += wtot[i];
    if (pred) act[prefix + __popc(bal & ((1u << lane) - 1u))] = tid;
    if (tid == 0) {
        int t = 0;
        for (int i = 0; i < 7; ++i) t += wtot[i];
        nact_s = t;
    }
    __syncthreads();
    const int nact = nact_s;

    // ---- resolve compacted global row index per active s ----
    if (tid < nact) {
        int s = act[tid];
        act_row[tid] = s * B_ + g_rank[s * B_ + b];
    }
    for (int x = tid; x < NI_ * S_; x += RT_THREADS) cw_s[x] = 0.f;
    __syncthreads();

    // ---- bulk cp.async load of active hat rows into smem ----
    uint32_t smem_b = (uint32_t)__cvta_generic_to_shared(hat_s);
    for (int x4 = tid; x4 < nact * 64; x4 += RT_THREADS) {
        int c = x4 >> 6, e4 = (x4 & 63) << 2;
        const float* src = g_hat + ((size_t)act_row[c] << 8) + e4;
        CP_ASYNC16(smem_b + (uint32_t)(c * HPAD + e4) * 4, src);
    }
    CP_COMMIT_WAIT();
    __syncthreads();

    const int k = tid >> 7;           // 0..3
    const int d = (tid >> 1) & 63;    // pair shares (k,d)
    const int half = tid & 1;
    const int off = k * 64 + d;
    const int hn = (nact + 1) >> 1;
    const int g8 = lane >> 2, q4 = lane & 3;     // cw-update layout
    float capv = 0.f;

    for (int it = 0; it < 3; ++it) {
        if (tid < nact) {
            float c0 = cw_s[0 * S_ + tid], c1 = cw_s[1 * S_ + tid];
            float c2 = cw_s[2 * S_ + tid], c3 = cw_s[3 * S_ + tid];
            float mx = fmaxf(fmaxf(c0, c1), fmaxf(c2, c3));
            float e0 = __expf(c0 - mx), e1 = __expf(c1 - mx);
            float e2 = __expf(c2 - mx), e3 = __expf(c3 - mx);
            float inv = 1.0f / (e0 + e1 + e2 + e3);
            sw_s[0 * S_ + tid] = e0 * inv;
            sw_s[1 * S_ + tid] = e1 * inv;
            sw_s[2 * S_ + tid] = e2 * inv;
            sw_s[3 * S_ + tid] = e3 * inv;
        }
        __syncthreads();

        // v[k,d] = sum_c sw[k,c]*hat[c, off]; c-range split across pair
        float v = 0.f;
        const float* swk = &sw_s[k * S_];
        const int cbeg = half * hn;
        const int cend = (cbeg + hn < nact) ? cbeg + hn : nact;
        #pragma unroll 4
        for (int c = cbeg; c < cend; ++c)
            v += swk[c] * hat_s[c * HPAD + off];
        v += __shfl_xor_sync(0xffffffffu, v, 1);     // both halves: full sum

        float p = half ? 0.f : v * v;
        #pragma unroll
        for (int o = 16; o; o >>= 1) p += __shfl_xor_sync(0xffffffffu, p, o);
        if (lane == 0) wsum[wrp] = p;
        __syncthreads();
        float n = wsum[4 * k] + wsum[4 * k + 1] + wsum[4 * k + 2] + wsum[4 * k + 3];
        float scale = n / (1.0f + n) / sqrtf(n + 1e-9f);
        capv = scale * v;
        if (!half) cap_s[off] = capv;
        __syncthreads();

        if (it < 2) {
            // cw[kk,c] += hat[c, kk*64:] . cap[kk,:]
            // 4 lanes per dot (q4): banks 4g8+q4 all distinct, conflict-free.
            const int ndots = NI_ * nact;
            for (int j0 = wrp * 8; j0 < ndots; j0 += 16 * 8) {
                int j = j0 + g8;
                float p2 = 0.f;
                int kk = 0, c = 0;
                if (j < ndots) {
                    kk = j / nact; c = j - kk * nact;
                    const float* hr = &hat_s[c * HPAD + kk * 64 + q4];
                    const float* cr = &cap_s[kk * 64 + q4];
                    #pragma unroll
                    for (int i = 0; i < 16; ++i)
                        p2 += hr[4 * i] * cr[4 * i];
                }
                p2 += __shfl_xor_sync(0xffffffffu, p2, 1);
                p2 += __shfl_xor_sync(0xffffffffu, p2, 2);
                if (j < ndots && q4 == 0) cw_s[kk * S_ + c] += p2;
            }
            __syncthreads();
        }
    }

    if (!half) out_interest[(size_t)b * E_ + off] = capv;
}

// ====================================================================
// launch — critical path (hat->route) on a HIGH-PRIORITY stream;
//          adj overlaps on the default stream.
// ====================================================================
extern "C" void kernel_launch(void* const* d_in, const int* in_sizes, int n_in,
                              void* d_out, int out_size)
{
    const int*   uid      = (const int*)  d_in[0];
    const int*   age      = (const int*)  d_in[1];
    const int*   gender   = (const int*)  d_in[2];
    const int*   occup    = (const int*)  d_in[3];
    const int*   mid_his  = (const int*)  d_in[4];
    const float* mask     = (const float*)d_in[5];
    const float* ue       = (const float*)d_in[6];
    const float* at       = (const float*)d_in[7];
    const float* gt       = (const float*)d_in[8];
    const float* ot       = (const float*)d_in[9];
    const float* mid_emb  = (const float*)d_in[10];
    const float* w        = (const float*)d_in[11];
    float* out = (float*)d_out;

    static cudaStream_t s2 = nullptr;
    static cudaEvent_t ev_fork = nullptr, ev_join = nullptr;
    if (!s2) {
        int lo, hi;
        cudaDeviceGetStreamPriorityRange(&lo, &hi);
        cudaStreamCreateWithPriority(&s2, cudaStreamNonBlocking, hi);
        cudaEventCreateWithFlags(&ev_fork, cudaEventDisableTiming);
        cudaEventCreateWithFlags(&ev_join, cudaEventDisableTiming);
        cudaFuncSetAttribute(route_kernel,
                             cudaFuncAttributeMaxDynamicSharedMemorySize, ROUTE_SMEM);
        cudaFuncSetAttribute(adj_kernel,
                             cudaFuncAttributeMaxDynamicSharedMemorySize, SMEM_GEMM_BYTES);
        cudaFuncSetAttribute(hat_kernel,
                             cudaFuncAttributeMaxDynamicSharedMemorySize, SMEM_GEMM_BYTES);
    }

    uprof_kernel<<<B_ * D_ / 256, 256>>>(uid, age, gender, occup, ue, at, gt, ot);
    gather_kernel<<<B_ * S_ * 16 / 256, 256>>>(mid_his, mask, mid_emb);

    cudaEventRecord(ev_fork, 0);
    cudaStreamWaitEvent(s2, ev_fork, 0);

    hat_kernel<<<dim3(2, B_ / 128, S_), 256, SMEM_GEMM_BYTES, s2>>>(w);
    route_kernel<<<B_, RT_THREADS, ROUTE_SMEM, s2>>>(mask, out);

    adj_kernel<<<dim3(2, 2, B_), 256, SMEM_GEMM_BYTES>>>(mask, out + INTEREST_ELEMS);

    cudaEventRecord(ev_join, s2);
    cudaStreamWaitEvent(0, ev_join, 0);
}

// round 13
// speedup vs baseline: 1.1047x; 1.0069x over previous
#include <cuda_runtime.h>
#include <cstdint>

// ---------------- problem constants ----------------
#define B_   1024
#define S_   200
#define D_   64
#define NI_  4
#define E_   256            // NI * D
#define INTEREST_ELEMS (B_ * NI_ * D_)   // 262144, adj follows at this offset

// ---------------- device scratch (static; no runtime alloc) ----------------
__device__ float g_uprof[B_ * D_];                       // 256 KB
__device__ float g_item[(long long)B_ * S_ * D_];        // 52.4 MB
__device__ float g_hat [(long long)S_ * B_ * E_];        // 209.7 MB, [s][rank][e]
__device__ int   g_cnt [S_];                             // active-b count per s
__device__ int   g_blist[S_ * B_];                       // [s][rank] -> b
__device__ int   g_rank [S_ * B_];                       // [s][b] -> rank

// ---------------- cp.async / cluster helpers ----------------
#define CP_ASYNC16(dst_u32, src_ptr) \
    asm volatile("cp.async.cg.shared.global [%0], [%1], 16;" \
                 :: "r"(dst_u32), "l"(src_ptr))
#define CP_COMMIT_WAIT() \
    asm volatile("cp.async.commit_group;\ncp.async.wait_group 0;" ::: "memory")

#define CLUSTER_SYNC() do { \
    asm volatile("barrier.cluster.arrive.aligned;" ::: "memory"); \
    asm volatile("barrier.cluster.wait.aligned;" ::: "memory"); \
} while (0)

// store val to the SAME smem offset in peer CTA of the cluster
#define ST_CLUSTER_F32(addr_u32, peer, val) \
    asm volatile("{\n\t.reg .b32 r;\n\t" \
                 "mapa.shared::cluster.u32 r, %0, %1;\n\t" \
                 "st.shared::cluster.f32 [r], %2;\n\t}" \
                 :: "r"(addr_u32), "r"(peer), "f"(val) : "memory")

__device__ __forceinline__ uint32_t ctarank() {
    uint32_t r;
    asm("mov.u32 %0, %%cluster_ctarank;" : "=r"(r));
    return r;
}

// ---------------- tf32 mma helpers ----------------
__device__ __forceinline__ uint32_t f2tf(float x) {
    uint32_t u;
    asm("cvt.rna.tf32.f32 %0, %1;" : "=r"(u) : "f"(x));
    return u;
}

__device__ __forceinline__ void mma8(float* d, const uint32_t* a,
                                     uint32_t b0, uint32_t b1) {
    asm volatile(
        "mma.sync.aligned.m16n8k8.row.col.f32.tf32.tf32.f32 "
        "{%0,%1,%2,%3}, {%4,%5,%6,%7}, {%8,%9}, {%0,%1,%2,%3};"
        : "+f"(d[0]), "+f"(d[1]), "+f"(d[2]), "+f"(d[3])
        : "r"(a[0]), "r"(a[1]), "r"(a[2]), "r"(a[3]), "r"(b0), "r"(b1));
}

#define LDA 68     // smem row stride (uint32); conflict-free fragment LDS
#define SMEM_GEMM_BYTES (2 * 128 * LDA * 4)   // 69632

// 128x128x64 block tile, 8 warps of 32x64 each.
__device__ __forceinline__ void mma_core(const uint32_t* __restrict__ As,
                                         const uint32_t* __restrict__ Bs,
                                         int tid, float acc[2][8][4]) {
    const int lane = tid & 31, wid = tid >> 5;
    const int g = lane >> 2, t = lane & 3;
    const int m0 = (wid & 3) * 32, n0 = (wid >> 2) * 64;
    #pragma unroll
    for (int k0 = 0; k0 < 64; k0 += 8) {
        uint32_t a[2][4];
        #pragma unroll
        for (int mf = 0; mf < 2; ++mf) {
            const uint32_t* p = As + (m0 + 16 * mf + g) * LDA + k0 + t;
            a[mf][0] = p[0];
            a[mf][1] = p[8 * LDA];
            a[mf][2] = p[4];
            a[mf][3] = p[8 * LDA + 4];
        }
        #pragma unroll
        for (int nf = 0; nf < 8; ++nf) {
            const uint32_t* p = Bs + (n0 + 8 * nf + g) * LDA + k0 + t;
            uint32_t b0v = p[0], b1v = p[4];
            mma8(acc[0][nf], a[0], b0v, b1v);
            mma8(acc[1][nf], a[1], b0v, b1v);
        }
    }
}

// ====================================================================
// K1: user profile (+ zero the per-s active counters)
// ====================================================================
__global__ __launch_bounds__(256) void uprof_kernel(
    const int* __restrict__ uid, const int* __restrict__ age,
    const int* __restrict__ gender, const int* __restrict__ occup,
    const float* __restrict__ ue, const float* __restrict__ at,
    const float* __restrict__ gt, const float* __restrict__ ot)
{
    if (blockIdx.x == 0 && threadIdx.x < S_) g_cnt[threadIdx.x] = 0;
    int idx = blockIdx.x * 256 + threadIdx.x;
    int b = idx >> 6, d = idx & 63;
    float v = ue[(size_t)uid[b]    * 64 + d]
            + gt[(size_t)gender[b] * 64 + d]
            + at[(size_t)age[b]    * 64 + d]
            + ot[(size_t)occup[b]  * 64 + d];
    g_uprof[idx] = 0.25f * v;
}

// ====================================================================
// K2: item_his = mid_emb[mid_his]*mask  (+ build per-s active-b lists)
// ====================================================================
__global__ __launch_bounds__(256) void gather_kernel(
    const int* __restrict__ mid_his, const float* __restrict__ mask,
    const float* __restrict__ mid_emb)
{
    int t  = blockIdx.x * 256 + threadIdx.x;
    int bs = t >> 4, q = t & 15;
    int mi = mid_his[bs];
    float m = mask[bs];
    float4 e = ((const float4*)mid_emb)[(size_t)mi * 16 + q];
    float4 it;
    it.x = e.x * m;  it.y = e.y * m;  it.z = e.z * m;  it.w = e.w * m;
    ((float4*)g_item)[(size_t)bs * 16 + q] = it;

    if (q == 0 && m != 0.f) {
        int b = bs / S_, s = bs - b * S_;
        int r = atomicAdd(&g_cnt[s], 1);
        g_blist[s * B_ + r] = b;
        g_rank [s * B_ + b] = r;
    }
}

// ====================================================================
// K3: adj — tf32 tensor cores, ROW-COMPACTED (active i only)
// ====================================================================
__global__ __launch_bounds__(256) void adj_kernel(
    const float* __restrict__ mask, float* __restrict__ out)
{
    extern __shared__ uint32_t sh[];
    uint32_t* As = sh;
    uint32_t* Bs = sh + 128 * LDA;
    __shared__ float msk[256];
    __shared__ int act[S_], inact[S_];
    __shared__ int wtotA[8], wtotI[8];
    __shared__ int nact_s;

    const int b  = blockIdx.z;
    const int i0 = blockIdx.y * 128;       // compacted-row tile origin
    const int j0 = blockIdx.x * 128;
    const int tid = threadIdx.x;
    const int lane = tid & 31, wrp = tid >> 5;
    const float* It = g_item + (size_t)b * (S_ * D_);
    float* outb = out + (size_t)b * (S_ * S_);

    float mval = (tid < S_) ? mask[b * S_ + tid] : 0.f;
    msk[tid] = mval;

    int predA = (tid < S_) && (mval != 0.f);
    int predI = (tid < S_) && (mval == 0.f);
    unsigned balA = __ballot_sync(0xffffffffu, predA);
    unsigned balI = __ballot_sync(0xffffffffu, predI);
    if (lane == 0) { wtotA[wrp] = __popc(balA); wtotI[wrp] = __popc(balI); }
    __syncthreads();
    int pA = 0, pI = 0;
    for (int i = 0; i < wrp; ++i) { pA += wtotA[i]; pI += wtotI[i]; }
    unsigned ltm = (1u << lane) - 1u;
    if (predA) act[pA + __popc(balA & ltm)] = tid;
    if (predI) inact[pI + __popc(balI & ltm)] = tid;
    if (tid == 0) {
        int t = 0;
        for (int i = 0; i < 7; ++i) t += wtotA[i];
        nact_s = t;
    }
    __syncthreads();
    const int nact = nact_s;

    if (blockIdx.y == 1) {
        int ninact = S_ - nact;
        int jw = (j0 + 128 <= S_) ? 128 : (S_ - j0);
        int nf4 = jw >> 2;
        for (int x = tid; x < ninact * nf4; x += 256) {
            int r = x / nf4, c4 = x - r * nf4;
            *(float4*)(outb + (size_t)inact[r] * S_ + j0 + c4 * 4) =
                make_float4(0.f, 0.f, 0.f, 0.f);
        }
    }
    if (i0 >= nact) return;

    #pragma unroll
    for (int p = 0; p < 8; ++p) {
        int q = tid + p * 256;
        int r = q >> 4, c4 = q & 15;
        float4 up = ((const float4*)g_uprof)[b * 16 + c4];
        float4 av = make_float4(0.f, 0.f, 0.f, 0.f);
        float4 bv = make_float4(0.f, 0.f, 0.f, 0.f);
        if (i0 + r < nact) {
            float4 iv = *(const float4*)(It + (size_t)act[i0 + r] * 64 + c4 * 4);
            av.x = iv.x * up.x; av.y = iv.y * up.y;
            av.z = iv.z * up.z; av.w = iv.w * up.w;
        }
        if (j0 + r < S_) bv = *(const float4*)(It + (size_t)(j0 + r) * 64 + c4 * 4);
        uint4 at4 = make_uint4(f2tf(av.x), f2tf(av.y), f2tf(av.z), f2tf(av.w));
        uint4 bt4 = make_uint4(f2tf(bv.x), f2tf(bv.y), f2tf(bv.z), f2tf(bv.w));
        *(uint4*)(As + r * LDA + c4 * 4) = at4;
        *(uint4*)(Bs + r * LDA + c4 * 4) = bt4;
    }
    __syncthreads();

    float acc[2][8][4] = {};
    mma_core(As, Bs, tid, acc);

    const int g = lane >> 2, t = lane & 3;
    const int wid = tid >> 5;
    const int m0 = (wid & 3) * 32, n0 = (wid >> 2) * 64;

    #pragma unroll
    for (int mf = 0; mf < 2; ++mf) {
        #pragma unroll
        for (int nf = 0; nf < 8; ++nf) {
            int ci = i0 + m0 + 16 * mf + g;
            int j  = j0 + n0 + 8 * nf + 2 * t;
            if (j < S_) {
                float mj0 = msk[j], mj1 = msk[j + 1];
                if (ci < nact) {
                    int i = act[ci];
                    float s0 = 1.f / (1.f + __expf(-acc[mf][nf][0]));
                    float s1 = 1.f / (1.f + __expf(-acc[mf][nf][1]));
                    *(float2*)(outb + (size_t)i * S_ + j) =
                        make_float2(s0 * mj0, s1 * mj1);
                }
                if (ci + 8 < nact) {
                    int i = act[ci + 8];
                    float s2 = 1.f / (1.f + __expf(-acc[mf][nf][2]));
                    float s3 = 1.f / (1.f + __expf(-acc[mf][nf][3]));
                    *(float2*)(outb + (size_t)i * S_ + j) =
                        make_float2(s2 * mj0, s3 * mj1);
                }
            }
        }
    }
}

// ====================================================================
// K4: hat — tf32 tensor cores, ACTIVE b-rows only, compacted output.
// ====================================================================
__global__ __launch_bounds__(256) void hat_kernel(const float* __restrict__ w)
{
    const int s   = blockIdx.z;
    const int cnt = g_cnt[s];
    const int b0  = blockIdx.y * 128;
    if (b0 >= cnt) return;
    const int e0  = blockIdx.x * 128;
    const int tid = threadIdx.x;

    extern __shared__ uint32_t sh[];
    uint32_t* As = sh;
    uint32_t* Bs = sh + 128 * LDA;

    #pragma unroll
    for (int p = 0; p < 8; ++p) {
        int q = tid + p * 256;
        int r = q >> 4, c4 = q & 15;
        float4 av = make_float4(0.f, 0.f, 0.f, 0.f);
        if (b0 + r < cnt) {
            int bidx = g_blist[s * B_ + b0 + r];
            av = *(const float4*)(g_item + ((size_t)bidx * S_ + s) * 64 + c4 * 4);
        }
        float4 bv = *(const float4*)(w + ((size_t)s * E_ + (e0 + r)) * 64 + c4 * 4);
        uint4 at4 = make_uint4(f2tf(av.x), f2tf(av.y), f2tf(av.z), f2tf(av.w));
        uint4 bt4 = make_uint4(f2tf(bv.x), f2tf(bv.y), f2tf(bv.z), f2tf(bv.w));
        *(uint4*)(As + r * LDA + c4 * 4) = at4;
        *(uint4*)(Bs + r * LDA + c4 * 4) = bt4;
    }
    __syncthreads();

    float acc[2][8][4] = {};
    mma_core(As, Bs, tid, acc);

    const int lane = tid & 31, wid = tid >> 5;
    const int g = lane >> 2, t = lane & 3;
    const int m0 = (wid & 3) * 32, n0 = (wid >> 2) * 64;

    #pragma unroll
    for (int mf = 0; mf < 2; ++mf) {
        #pragma unroll
        for (int nf = 0; nf < 8; ++nf) {
            int ri = b0 + m0 + 16 * mf + g;
            int e  = e0 + n0 + 8 * nf + 2 * t;
            if (ri < cnt)
                *(float2*)(g_hat + ((size_t)s * B_ + ri) * E_ + e) =
                    make_float2(acc[mf][nf][0], acc[mf][nf][1]);
            if (ri + 8 < cnt)
                *(float2*)(g_hat + ((size_t)s * B_ + ri + 8) * E_ + e) =
                    make_float2(acc[mf][nf][2], acc[mf][nf][3]);
        }
    }
}

// ====================================================================
// K5: routing, 2-CTA CLUSTER per batch (c-split). Each CTA owns half
//     the active rows (<=100 -> 104 KB smem -> 2 blocks/SM). Per-iter:
//     local partial v -> DSMEM exchange (256 floats) -> cluster barrier
//     -> squash (redundant) -> local cw-update. cw never crosses CTAs.
// ====================================================================
#define HPAD 260          // floats per smem row (1040 B)
#define HN_MAX 100        // worst-case rows per CTA (ceil(200/2))
#define ROUTE_SMEM (HN_MAX * HPAD * 4)   // 104000 B
#define RT_THREADS 512
__global__ __launch_bounds__(RT_THREADS) __cluster_dims__(2, 1, 1)
void route_kernel(const float* __restrict__ mask,
                  float* __restrict__ out_interest)
{
    extern __shared__ float hat_s[];                 // [cn][260]
    __shared__ float cw_s[NI_ * HN_MAX];
    __shared__ float sw_s[NI_ * HN_MAX];
    __shared__ float cap_s[E_];
    __shared__ float vbuf[2][E_];                    // peer partial-v slots
    __shared__ float wsum[16];
    __shared__ int   act[S_];
    __shared__ int   act_row[S_];
    __shared__ int   wtot[16];
    __shared__ int   nact_s;

    const int b = blockIdx.x >> 1;
    const uint32_t rank = ctarank();
    const uint32_t peer = rank ^ 1u;
    const int tid = threadIdx.x;
    const int lane = tid & 31, wrp = tid >> 5;

    // ---- deterministic compaction of active s (mask != 0) ----
    int pred = (tid < S_) ? (mask[b * S_ + tid] != 0.f) : 0;
    unsigned bal = __ballot_sync(0xffffffffu, pred);
    if (lane == 0) wtot[wrp] = __popc(bal);
    __syncthreads();
    int prefix = 0;
    for (int i = 0; i < wrp && i < 7; ++i) prefix += wtot[i];
    if (pred) act[prefix + __popc(bal & ((1u << lane) - 1u))] = tid;
    if (tid == 0) {
        int t = 0;
        for (int i = 0; i < 7; ++i) t += wtot[i];
        nact_s = t;
    }
    __syncthreads();
    const int nact = nact_s;
    const int hn = (nact + 1) >> 1;                  // rows per rank
    const int cbase = (int)rank * hn;
    const int cn = (cbase + hn <= nact) ? hn : (nact - cbase);  // my rows

    // ---- resolve compacted global row index (full list; cheap) ----
    if (tid < nact) {
        int s = act[tid];
        act_row[tid] = s * B_ + g_rank[s * B_ + b];
    }
    for (int x = tid; x < NI_ * HN_MAX; x += RT_THREADS) cw_s[x] = 0.f;
    __syncthreads();

    // ---- cp.async load of MY half of active hat rows ----
    uint32_t smem_b = (uint32_t)__cvta_generic_to_shared(hat_s);
    for (int x4 = tid; x4 < cn * 64; x4 += RT_THREADS) {
        int c = x4 >> 6, e4 = (x4 & 63) << 2;
        const float* src = g_hat + ((size_t)act_row[cbase + c] << 8) + e4;
        CP_ASYNC16(smem_b + (uint32_t)(c * HPAD + e4) * 4, src);
    }
    CP_COMMIT_WAIT();
    __syncthreads();

    const int k = tid >> 7;           // 0..3
    const int d = (tid >> 1) & 63;    // pair shares (k,d)
    const int half = tid & 1;
    const int off = k * 64 + d;
    const int g8 = lane >> 2, q4 = lane & 3;     // cw-update layout
    const uint32_t vbuf_sh = (uint32_t)__cvta_generic_to_shared(vbuf);
    float capv = 0.f;

    for (int it = 0; it < 3; ++it) {
        // softmax over k at my active positions
        if (tid < cn) {
            float c0 = cw_s[0 * HN_MAX + tid], c1 = cw_s[1 * HN_MAX + tid];
            float c2 = cw_s[2 * HN_MAX + tid], c3 = cw_s[3 * HN_MAX + tid];
            float mx = fmaxf(fmaxf(c0, c1), fmaxf(c2, c3));
            float e0 = __expf(c0 - mx), e1 = __expf(c1 - mx);
            float e2 = __expf(c2 - mx), e3 = __expf(c3 - mx);
            float inv = 1.0f / (e0 + e1 + e2 + e3);
            sw_s[0 * HN_MAX + tid] = e0 * inv;
            sw_s[1 * HN_MAX + tid] = e1 * inv;
            sw_s[2 * HN_MAX + tid] = e2 * inv;
            sw_s[3 * HN_MAX + tid] = e3 * inv;
        }
        __syncthreads();

        // local partial v[k,d] over my cn rows; pair-split then shfl
        float v = 0.f;
        const float* swk = &sw_s[k * HN_MAX];
        const int pn = (cn + 1) >> 1;
        const int cbeg = half * pn;
        const int cend = (cbeg + pn < cn) ? cbeg + pn : cn;
        #pragma unroll 4
        for (int c = cbeg; c < cend; ++c)
            v += swk[c] * hat_s[c * HPAD + off];
        v += __shfl_xor_sync(0xffffffffu, v, 1);     // my-half partial sum

        // exchange partials via peer smem; one cluster barrier
        const int slot = it & 1;
        if (!half)
            ST_CLUSTER_F32(vbuf_sh + (uint32_t)(slot * E_ + off) * 4, peer, v);
        CLUSTER_SYNC();
        float vf = v + vbuf[slot][off];              // full v[k,d]

        // squash (computed redundantly in both CTAs)
        float p = half ? 0.f : vf * vf;
        #pragma unroll
        for (int o = 16; o; o >>= 1) p += __shfl_xor_sync(0xffffffffu, p, o);
        if (lane == 0) wsum[wrp] = p;
        __syncthreads();
        float n = wsum[4 * k] + wsum[4 * k + 1] + wsum[4 * k + 2] + wsum[4 * k + 3];
        float scale = n / (1.0f + n) / sqrtf(n + 1e-9f);
        capv = scale * vf;
        if (!half) cap_s[off] = capv;
        __syncthreads();

        if (it < 2) {
            // cw[kk,c] += hat[c, kk*64:] . cap[kk,:]  (my rows only)
            // 4 lanes per dot: banks 4g8+q4 distinct -> conflict-free.
            const int ndots = NI_ * cn;
            for (int j0 = wrp * 8; j0 < ndots; j0 += 16 * 8) {
                int j = j0 + g8;
                float p2 = 0.f;
                int kk = 0, c = 0;
                if (j < ndots) {
                    kk = j / cn; c = j - kk * cn;
                    const float* hr = &hat_s[c * HPAD + kk * 64 + q4];
                    const float* cr = &cap_s[kk * 64 + q4];
                    #pragma unroll
                    for (int i = 0; i < 16; ++i)
                        p2 += hr[4 * i] * cr[4 * i];
                }
                p2 += __shfl_xor_sync(0xffffffffu, p2, 1);
                p2 += __shfl_xor_sync(0xffffffffu, p2, 2);
                if (j < ndots && q4 == 0) cw_s[kk * HN_MAX + c] += p2;
            }
            __syncthreads();
        }
    }

    if (rank == 0 && !half) out_interest[(size_t)b * E_ + off] = capv;
}

// ====================================================================
// launch — critical path (hat->route) on a HIGH-PRIORITY stream;
//          adj overlaps on the default stream.
// ====================================================================
extern "C" void kernel_launch(void* const* d_in, const int* in_sizes, int n_in,
                              void* d_out, int out_size)
{
    const int*   uid      = (const int*)  d_in[0];
    const int*   age      = (const int*)  d_in[1];
    const int*   gender   = (const int*)  d_in[2];
    const int*   occup    = (const int*)  d_in[3];
    const int*   mid_his  = (const int*)  d_in[4];
    const float* mask     = (const float*)d_in[5];
    const float* ue       = (const float*)d_in[6];
    const float* at       = (const float*)d_in[7];
    const float* gt       = (const float*)d_in[8];
    const float* ot       = (const float*)d_in[9];
    const float* mid_emb  = (const float*)d_in[10];
    const float* w        = (const float*)d_in[11];
    float* out = (float*)d_out;

    static cudaStream_t s2 = nullptr;
    static cudaEvent_t ev_fork = nullptr, ev_join = nullptr;
    if (!s2) {
        int lo, hi;
        cudaDeviceGetStreamPriorityRange(&lo, &hi);
        cudaStreamCreateWithPriority(&s2, cudaStreamNonBlocking, hi);
        cudaEventCreateWithFlags(&ev_fork, cudaEventDisableTiming);
        cudaEventCreateWithFlags(&ev_join, cudaEventDisableTiming);
        cudaFuncSetAttribute(route_kernel,
                             cudaFuncAttributeMaxDynamicSharedMemorySize, ROUTE_SMEM);
        cudaFuncSetAttribute(adj_kernel,
                             cudaFuncAttributeMaxDynamicSharedMemorySize, SMEM_GEMM_BYTES);
        cudaFuncSetAttribute(hat_kernel,
                             cudaFuncAttributeMaxDynamicSharedMemorySize, SMEM_GEMM_BYTES);
    }

    uprof_kernel<<<B_ * D_ / 256, 256>>>(uid, age, gender, occup, ue, at, gt, ot);
    gather_kernel<<<B_ * S_ * 16 / 256, 256>>>(mid_his, mask, mid_emb);

    cudaEventRecord(ev_fork, 0);
    cudaStreamWaitEvent(s2, ev_fork, 0);

    hat_kernel<<<dim3(2, B_ / 128, S_), 256, SMEM_GEMM_BYTES, s2>>>(w);
    route_kernel<<<2 * B_, RT_THREADS, ROUTE_SMEM, s2>>>(mask, out);

    adj_kernel<<<dim3(2, 2, B_), 256, SMEM_GEMM_BYTES>>>(mask, out + INTEREST_ELEMS);

    cudaEventRecord(ev_join, s2);
    cudaStreamWaitEvent(0, ev_join, 0);
}